// round 1
// baseline (speedup 1.0000x reference)
#include <cuda_runtime.h>

// Key space: 64^4 = 2^24 keys -> bitmap of 2^24 bits = 2^19 32-bit words = 2 MB.
#define WORDS        (1u << 19)
#define SCAN_BLOCKS  512
#define SCAN_THREADS 1024   // SCAN_BLOCKS * SCAN_THREADS == WORDS

// Scratch (device globals: no allocation allowed in kernel_launch).
__device__ unsigned int g_bitmap[WORDS];        // presence bits per key
__device__ unsigned int g_wordPrefix[WORDS];    // exclusive popcount prefix within scan block
__device__ unsigned int g_blockSums[SCAN_BLOCKS];
__device__ unsigned int g_blockOffsets[SCAN_BLOCKS];

// ---------------------------------------------------------------------------
// 0) zero the bitmap (must be reset every launch: graph replays reuse it)
__global__ void zero_bitmap_kernel() {
    unsigned i = blockIdx.x * blockDim.x + threadIdx.x;   // WORDS/4 uint4 stores
    ((uint4*)g_bitmap)[i] = make_uint4(0, 0, 0, 0);
}

// 1) zero the output (poisoned to 0xAA by the harness; padding rows must be 0,
//    and the scatter accumulates with atomics from a zero base)
__global__ void zero_out_kernel(float4* __restrict__ out, int n4) {
    int i = blockIdx.x * blockDim.x + threadIdx.x;
    if (i < n4) out[i] = make_float4(0.f, 0.f, 0.f, 0.f);
}

// 2) mark key presence
__device__ __forceinline__ unsigned make_key(int4 c) {
    return (unsigned)(((c.x * 64 + c.y) * 64 + c.z) * 64 + c.w);   // < 2^24
}

__global__ void set_bits_kernel(const int4* __restrict__ coords, int n) {
    int i = blockIdx.x * blockDim.x + threadIdx.x;
    if (i < n) {
        unsigned key = make_key(coords[i]);
        atomicOr(&g_bitmap[key >> 5], 1u << (key & 31));
    }
}

// 3) per-block scan of word popcounts: writes exclusive-within-block prefix per
//    word and the block total.
__global__ void block_scan_kernel() {
    __shared__ unsigned warpSums[32];
    unsigned w = blockIdx.x * SCAN_THREADS + threadIdx.x;
    unsigned p = __popc(g_bitmap[w]);

    // warp inclusive scan
    unsigned v = p;
    int lane = threadIdx.x & 31;
    int warp = threadIdx.x >> 5;
    #pragma unroll
    for (int d = 1; d < 32; d <<= 1) {
        unsigned t = __shfl_up_sync(0xffffffffu, v, d);
        if (lane >= d) v += t;
    }
    if (lane == 31) warpSums[warp] = v;
    __syncthreads();
    if (warp == 0) {
        unsigned s = warpSums[lane];
        #pragma unroll
        for (int d = 1; d < 32; d <<= 1) {
            unsigned t = __shfl_up_sync(0xffffffffu, s, d);
            if (lane >= d) s += t;
        }
        warpSums[lane] = s;   // inclusive warp totals
    }
    __syncthreads();
    unsigned base = (warp > 0) ? warpSums[warp - 1] : 0u;
    g_wordPrefix[w] = base + v - p;                        // exclusive prefix
    if (threadIdx.x == SCAN_THREADS - 1)
        g_blockSums[blockIdx.x] = base + v;                // block total
}

// 4) exclusive scan of the 512 block totals (single block)
__global__ void scan_blocksums_kernel() {
    __shared__ unsigned warpSums[16];
    int t = threadIdx.x;                 // 512 threads
    int lane = t & 31, warp = t >> 5;    // 16 warps
    unsigned p = g_blockSums[t];
    unsigned v = p;
    #pragma unroll
    for (int d = 1; d < 32; d <<= 1) {
        unsigned x = __shfl_up_sync(0xffffffffu, v, d);
        if (lane >= d) v += x;
    }
    if (lane == 31) warpSums[warp] = v;
    __syncthreads();
    if (warp == 0 && lane < 16) {
        unsigned s = warpSums[lane];
        #pragma unroll
        for (int d = 1; d < 16; d <<= 1) {
            unsigned x = __shfl_up_sync(0x0000ffffu, s, d);
            if (lane >= d) s += x;
        }
        warpSums[lane] = s;
    }
    __syncthreads();
    unsigned base = (warp > 0) ? warpSums[warp - 1] : 0u;
    g_blockOffsets[t] = base + v - p;    // exclusive
}

// 5) scatter: one warp per point, lane == channel (C == 32).
//    rank = global exclusive count of set bits strictly below `key`
//         == position of key in ascending sorted unique array.
__global__ void scatter_kernel(const int4* __restrict__ coords,
                               const float* __restrict__ feat,
                               float* __restrict__ out, int n) {
    int gtid   = blockIdx.x * blockDim.x + threadIdx.x;
    int warpId = gtid >> 5;
    int lane   = gtid & 31;
    if (warpId >= n) return;

    unsigned rank = 0;
    if (lane == 0) {
        unsigned key = make_key(coords[warpId]);
        unsigned w   = key >> 5;
        unsigned bit = key & 31;
        unsigned below = __popc(g_bitmap[w] & ((1u << bit) - 1u));
        rank = g_blockOffsets[w >> 10] + g_wordPrefix[w] + below;
    }
    rank = __shfl_sync(0xffffffffu, rank, 0);

    float v = feat[(size_t)warpId * 32 + lane];
    atomicAdd(&out[(size_t)rank * 32 + lane], v);
}

// ---------------------------------------------------------------------------
extern "C" void kernel_launch(void* const* d_in, const int* in_sizes, int n_in,
                              void* d_out, int out_size) {
    const int4*  coords = (const int4*)d_in[0];   // [N,4] int32, 16B rows
    const float* feat   = (const float*)d_in[1];  // [N,32] float32
    float*       out    = (float*)d_out;          // [N,32] float32
    int n = in_sizes[0] / 4;

    zero_bitmap_kernel<<<(WORDS / 4) / 256, 256>>>();
    int n4 = out_size / 4;
    zero_out_kernel<<<(n4 + 255) / 256, 256>>>((float4*)out, n4);
    set_bits_kernel<<<(n + 255) / 256, 256>>>(coords, n);
    block_scan_kernel<<<SCAN_BLOCKS, SCAN_THREADS>>>();
    scan_blocksums_kernel<<<1, 512>>>();
    // one warp per point: n*32 threads
    long long threads = (long long)n * 32;
    scatter_kernel<<<(int)((threads + 255) / 256), 256>>>(coords, feat, out, n);
}

// round 2
// speedup vs baseline: 1.0948x; 1.0948x over previous
#include <cuda_runtime.h>

// Key space: 64^4 = 2^24 keys -> bitmap of 2^24 bits = 2^19 32-bit words = 2 MB.
#define WORDS        (1u << 19)
#define SCAN_BLOCKS  512
#define SCAN_THREADS 1024   // SCAN_BLOCKS * SCAN_THREADS == WORDS
#define MAXN         (1u << 20)   // >= N = 1,000,000

// Scratch (device globals: no allocation allowed anywhere).
__device__ unsigned int g_bitmap[WORDS];        // presence bits per key
__device__ unsigned int g_wordPrefix[WORDS];    // exclusive popcount prefix within scan block
__device__ unsigned int g_blockSums[SCAN_BLOCKS];
__device__ unsigned int g_blockOffsets[SCAN_BLOCKS];
__device__ unsigned int g_keyflag[MAXN];        // key | (isFirst << 31) per point
__device__ unsigned int g_dupList[MAXN];        // point indices of non-first duplicates
__device__ unsigned int g_dupCount;
__device__ unsigned int g_totalUnique;

// ---------------------------------------------------------------------------
// 0) zero the bitmap + counters (graph replays reuse the globals)
__global__ void zero_bitmap_kernel() {
    unsigned i = blockIdx.x * blockDim.x + threadIdx.x;   // WORDS/4 uint4 stores
    ((uint4*)g_bitmap)[i] = make_uint4(0, 0, 0, 0);
    if (i == 0) g_dupCount = 0;
}

__device__ __forceinline__ unsigned make_key(int4 c) {
    return (unsigned)(((c.x * 64 + c.y) * 64 + c.z) * 64 + c.w);   // < 2^24
}

// 1) mark key presence; classify each point as first-setter or duplicate
__global__ void set_bits_kernel(const int4* __restrict__ coords, int n) {
    int i = blockIdx.x * blockDim.x + threadIdx.x;
    if (i >= n) return;
    unsigned key = make_key(coords[i]);
    unsigned bit = 1u << (key & 31);
    unsigned old = atomicOr(&g_bitmap[key >> 5], bit);
    bool first = (old & bit) == 0u;
    g_keyflag[i] = key | (first ? 0x80000000u : 0u);
    if (!first) {
        unsigned d = atomicAdd(&g_dupCount, 1u);
        g_dupList[d] = (unsigned)i;
    }
}

// 2) per-block scan of word popcounts
__global__ void block_scan_kernel() {
    __shared__ unsigned warpSums[32];
    unsigned w = blockIdx.x * SCAN_THREADS + threadIdx.x;
    unsigned p = __popc(g_bitmap[w]);

    unsigned v = p;
    int lane = threadIdx.x & 31;
    int warp = threadIdx.x >> 5;
    #pragma unroll
    for (int d = 1; d < 32; d <<= 1) {
        unsigned t = __shfl_up_sync(0xffffffffu, v, d);
        if (lane >= d) v += t;
    }
    if (lane == 31) warpSums[warp] = v;
    __syncthreads();
    if (warp == 0) {
        unsigned s = warpSums[lane];
        #pragma unroll
        for (int d = 1; d < 32; d <<= 1) {
            unsigned t = __shfl_up_sync(0xffffffffu, s, d);
            if (lane >= d) s += t;
        }
        warpSums[lane] = s;   // inclusive warp totals
    }
    __syncthreads();
    unsigned base = (warp > 0) ? warpSums[warp - 1] : 0u;
    g_wordPrefix[w] = base + v - p;                        // exclusive prefix
    if (threadIdx.x == SCAN_THREADS - 1)
        g_blockSums[blockIdx.x] = base + v;                // block total
}

// 3) exclusive scan of the 512 block totals; also emit total unique count
__global__ void scan_blocksums_kernel() {
    __shared__ unsigned warpSums[16];
    int t = threadIdx.x;                 // 512 threads
    int lane = t & 31, warp = t >> 5;    // 16 warps
    unsigned p = g_blockSums[t];
    unsigned v = p;
    #pragma unroll
    for (int d = 1; d < 32; d <<= 1) {
        unsigned x = __shfl_up_sync(0xffffffffu, v, d);
        if (lane >= d) v += x;
    }
    if (lane == 31) warpSums[warp] = v;
    __syncthreads();
    if (warp == 0 && lane < 16) {
        unsigned s = warpSums[lane];
        #pragma unroll
        for (int d = 1; d < 16; d <<= 1) {
            unsigned x = __shfl_up_sync(0x0000ffffu, s, d);
            if (lane >= d) s += x;
        }
        warpSums[lane] = s;
    }
    __syncthreads();
    unsigned base = (warp > 0) ? warpSums[warp - 1] : 0u;
    g_blockOffsets[t] = base + v - p;    // exclusive
    if (t == 511) g_totalUnique = base + v;
}

// rank = global count of set bits strictly below `key` = sorted-unique position
__device__ __forceinline__ unsigned rank_of(unsigned key) {
    unsigned w = key >> 5, bit = key & 31;
    unsigned below = __popc(g_bitmap[w] & ((1u << bit) - 1u));
    return g_blockOffsets[w >> 10] + g_wordPrefix[w] + below;
}

// 4) first-setter scatter (plain stores, full 128B lines) + padding-row zero.
//    One warp per point index i; the same warp also owns out-row i for padding.
//    Scatter targets (rank < U) and padding rows (i >= U) are disjoint.
__global__ void scatter_first_kernel(const float* __restrict__ feat,
                                     float* __restrict__ out, int n) {
    int gtid = blockIdx.x * blockDim.x + threadIdx.x;
    int wid  = gtid >> 5;
    int lane = gtid & 31;
    if (wid >= n) return;

    unsigned kf = 0, U = 0;
    if (lane == 0) { kf = g_keyflag[wid]; U = g_totalUnique; }
    kf = __shfl_sync(0xffffffffu, kf, 0);
    U  = __shfl_sync(0xffffffffu, U, 0);

    if ((unsigned)wid >= U)
        out[(size_t)wid * 32 + lane] = 0.0f;      // padding row

    if (kf & 0x80000000u) {
        unsigned rank = 0;
        if (lane == 0) rank = rank_of(kf & 0x00FFFFFFu);
        rank = __shfl_sync(0xffffffffu, rank, 0);
        out[(size_t)rank * 32 + lane] = feat[(size_t)wid * 32 + lane];
    }
}

// 5) duplicates: ~3% of points; atomicAdd after the base stores (launch-ordered)
__global__ void scatter_dups_kernel(const float* __restrict__ feat,
                                    float* __restrict__ out) {
    unsigned totalWarps = (gridDim.x * blockDim.x) >> 5;
    unsigned wid  = (blockIdx.x * blockDim.x + threadIdx.x) >> 5;
    int lane = threadIdx.x & 31;
    unsigned cnt = g_dupCount;
    for (unsigned j = wid; j < cnt; j += totalWarps) {
        unsigned p = 0, rank = 0;
        if (lane == 0) {
            p = g_dupList[j];
            rank = rank_of(g_keyflag[p] & 0x00FFFFFFu);
        }
        p    = __shfl_sync(0xffffffffu, p, 0);
        rank = __shfl_sync(0xffffffffu, rank, 0);
        atomicAdd(&out[(size_t)rank * 32 + lane], feat[(size_t)p * 32 + lane]);
    }
}

// ---------------------------------------------------------------------------
extern "C" void kernel_launch(void* const* d_in, const int* in_sizes, int n_in,
                              void* d_out, int out_size) {
    const int4*  coords = (const int4*)d_in[0];   // [N,4] int32
    const float* feat   = (const float*)d_in[1];  // [N,32] float32
    float*       out    = (float*)d_out;          // [N,32] float32
    int n = in_sizes[0] / 4;

    zero_bitmap_kernel<<<(WORDS / 4) / 256, 256>>>();
    set_bits_kernel<<<(n + 255) / 256, 256>>>(coords, n);
    block_scan_kernel<<<SCAN_BLOCKS, SCAN_THREADS>>>();
    scan_blocksums_kernel<<<1, 512>>>();
    long long threads = (long long)n * 32;                 // one warp per point
    scatter_first_kernel<<<(int)((threads + 255) / 256), 256>>>(feat, out, n);
    scatter_dups_kernel<<<512, 256>>>(feat, out);          // persistent loop
}

// round 3
// speedup vs baseline: 1.9030x; 1.7382x over previous
#include <cuda_runtime.h>

// Key space: 64^4 = 2^24 keys -> bitmap of 2^24 bits = 2^19 32-bit words = 2 MB.
#define WORDS        (1u << 19)
#define SCAN_BLOCKS  512
#define SCAN_THREADS 1024   // SCAN_BLOCKS * SCAN_THREADS == WORDS
#define MAXN         (1u << 20)   // >= N = 1,000,000

__device__ unsigned int g_bitmap[WORDS];        // presence bits per key
__device__ unsigned int g_wordPrefix[WORDS];    // exclusive popcount prefix within scan block
__device__ unsigned int g_blockSums[SCAN_BLOCKS];
__device__ unsigned int g_blockOffsets[SCAN_BLOCKS];
__device__ unsigned int g_keyflag[MAXN];        // key | (isFirst << 31) per point
__device__ unsigned int g_dupList[MAXN];        // point indices of non-first duplicates
__device__ unsigned int g_dupCount;
__device__ unsigned int g_totalUnique;
__device__ unsigned int g_scanDone;             // blocks-finished counter for fused scan

// ---------------------------------------------------------------------------
// 0) zero bitmap + counters (graph replays reuse the globals)
__global__ void zero_bitmap_kernel() {
    unsigned i = blockIdx.x * blockDim.x + threadIdx.x;   // WORDS/4 uint4 stores
    ((uint4*)g_bitmap)[i] = make_uint4(0, 0, 0, 0);
    if (i == 0) { g_dupCount = 0; g_scanDone = 0; }
}

__device__ __forceinline__ unsigned make_key(int4 c) {
    return (unsigned)(((c.x * 64 + c.y) * 64 + c.z) * 64 + c.w);   // < 2^24
}

// 1) mark key presence; classify each point as first-setter or duplicate
__global__ void set_bits_kernel(const int4* __restrict__ coords, int n) {
    int i = blockIdx.x * blockDim.x + threadIdx.x;
    if (i >= n) return;
    unsigned key = make_key(coords[i]);
    unsigned bit = 1u << (key & 31);
    unsigned old = atomicOr(&g_bitmap[key >> 5], bit);
    bool first = (old & bit) == 0u;
    g_keyflag[i] = key | (first ? 0x80000000u : 0u);
    if (!first) {
        unsigned d = atomicAdd(&g_dupCount, 1u);
        g_dupList[d] = (unsigned)i;
    }
}

// 2) fused hierarchical scan: per-block popcount scan + (block 0 only) scan of
//    the 512 block sums. Deadlock-free: only block 0 spins, after publishing.
__global__ void fused_scan_kernel() {
    __shared__ unsigned warpSums[32];
    unsigned w = blockIdx.x * SCAN_THREADS + threadIdx.x;
    unsigned p = __popc(g_bitmap[w]);

    unsigned v = p;
    int lane = threadIdx.x & 31;
    int warp = threadIdx.x >> 5;
    #pragma unroll
    for (int d = 1; d < 32; d <<= 1) {
        unsigned t = __shfl_up_sync(0xffffffffu, v, d);
        if (lane >= d) v += t;
    }
    if (lane == 31) warpSums[warp] = v;
    __syncthreads();
    if (warp == 0) {
        unsigned s = warpSums[lane];
        #pragma unroll
        for (int d = 1; d < 32; d <<= 1) {
            unsigned t = __shfl_up_sync(0xffffffffu, s, d);
            if (lane >= d) s += t;
        }
        warpSums[lane] = s;   // inclusive warp totals
    }
    __syncthreads();
    unsigned base = (warp > 0) ? warpSums[warp - 1] : 0u;
    g_wordPrefix[w] = base + v - p;                        // exclusive prefix
    if (threadIdx.x == SCAN_THREADS - 1) {
        g_blockSums[blockIdx.x] = base + v;                // block total
        __threadfence();
        atomicAdd(&g_scanDone, 1u);
    }

    // Block 0, warp 0: wait for all block sums, then scan them.
    if (blockIdx.x == 0 && warp == 0) {
        if (lane == 0) {
            while (atomicAdd(&g_scanDone, 0u) < SCAN_BLOCKS) { /* spin */ }
        }
        __syncwarp();
        __threadfence();
        // 512 sums, 16 per lane (contiguous range per lane)
        unsigned loc[16];
        unsigned mySum = 0;
        #pragma unroll
        for (int j = 0; j < 16; j++) {
            loc[j] = g_blockSums[lane * 16 + j];
            mySum += loc[j];
        }
        // exclusive scan of per-lane sums across the warp
        unsigned inc = mySum;
        #pragma unroll
        for (int d = 1; d < 32; d <<= 1) {
            unsigned t = __shfl_up_sync(0xffffffffu, inc, d);
            if (lane >= d) inc += t;
        }
        unsigned run = inc - mySum;   // exclusive base for this lane's range
        #pragma unroll
        for (int j = 0; j < 16; j++) {
            g_blockOffsets[lane * 16 + j] = run;
            run += loc[j];
        }
        if (lane == 31) g_totalUnique = run;   // total set bits
    }
}

// rank = global count of set bits strictly below `key` = sorted-unique position
__device__ __forceinline__ unsigned rank_of(unsigned key) {
    unsigned w = key >> 5, bit = key & 31;
    unsigned below = __popc(g_bitmap[w] & ((1u << bit) - 1u));
    return g_blockOffsets[w >> 10] + g_wordPrefix[w] + below;
}

// 3) first-setter scatter, float4-vectorized: 8 lanes per row, 4 rows per warp.
//    Full 128B line per row as 8x STG.128; 4 independent random lines in
//    flight per warp. Also zeroes padding rows (disjoint from scatter targets).
__global__ void scatter_first_kernel(const float4* __restrict__ feat4,
                                     float4* __restrict__ out4, int n) {
    int gtid = blockIdx.x * blockDim.x + threadIdx.x;
    int wid  = gtid >> 5;             // warp index
    int lane = gtid & 31;
    int sub  = lane >> 3;             // which of 4 rows this lane serves
    int j    = lane & 7;              // float4 index within row (8 * 16B = 128B)
    int row  = wid * 4 + sub;
    if (row >= n) return;

    unsigned U = g_totalUnique;       // L2-resident broadcast load

    // leader lane of each 8-lane group fetches keyflag + rank
    unsigned kf = 0, rank = 0;
    if (j == 0) {
        kf = g_keyflag[row];
        if (kf & 0x80000000u) rank = rank_of(kf & 0x00FFFFFFu);
    }
    int src = lane & ~7;
    kf   = __shfl_sync(0xffffffffu, kf, src);
    rank = __shfl_sync(0xffffffffu, rank, src);

    if ((unsigned)row >= U)
        out4[(size_t)row * 8 + j] = make_float4(0.f, 0.f, 0.f, 0.f);

    if (kf & 0x80000000u)
        out4[(size_t)rank * 8 + j] = feat4[(size_t)row * 8 + j];
}

// 4) duplicates (~3% of points): atomicAdd after base stores (launch-ordered)
__global__ void scatter_dups_kernel(const float* __restrict__ feat,
                                    float* __restrict__ out) {
    unsigned totalWarps = (gridDim.x * blockDim.x) >> 5;
    unsigned wid  = (blockIdx.x * blockDim.x + threadIdx.x) >> 5;
    int lane = threadIdx.x & 31;
    unsigned cnt = g_dupCount;
    for (unsigned j = wid; j < cnt; j += totalWarps) {
        unsigned p = 0, rank = 0;
        if (lane == 0) {
            p = g_dupList[j];
            rank = rank_of(g_keyflag[p] & 0x00FFFFFFu);
        }
        p    = __shfl_sync(0xffffffffu, p, 0);
        rank = __shfl_sync(0xffffffffu, rank, 0);
        atomicAdd(&out[(size_t)rank * 32 + lane], feat[(size_t)p * 32 + lane]);
    }
}

// ---------------------------------------------------------------------------
extern "C" void kernel_launch(void* const* d_in, const int* in_sizes, int n_in,
                              void* d_out, int out_size) {
    const int4*   coords = (const int4*)d_in[0];    // [N,4] int32
    const float*  feat   = (const float*)d_in[1];   // [N,32] float32
    float*        out    = (float*)d_out;           // [N,32] float32
    int n = in_sizes[0] / 4;

    zero_bitmap_kernel<<<(WORDS / 4) / 256, 256>>>();              // idx 0
    set_bits_kernel<<<(n + 255) / 256, 256>>>(coords, n);          // idx 1
    fused_scan_kernel<<<SCAN_BLOCKS, SCAN_THREADS>>>();            // idx 2
    // 4 rows per warp, 8 warps per block -> 32 rows per block
    int blocks = (n + 31) / 32;
    scatter_first_kernel<<<blocks, 256>>>((const float4*)feat,     // idx 3
                                          (float4*)out, n);
    scatter_dups_kernel<<<512, 256>>>(feat, out);                  // idx 4
}

// round 4
// speedup vs baseline: 2.1944x; 1.1532x over previous
#include <cuda_runtime.h>

// Key space: 64^4 = 2^24 keys -> 2^19 32-bit words.
#define WORDS        (1u << 19)
#define SCAN_BLOCKS  512
#define SCAN_THREADS 1024   // SCAN_BLOCKS * SCAN_THREADS == WORDS
#define MAXN         (1u << 20)   // >= N = 1,000,000

// g_bp[w] = { presence bits, exclusive popcount prefix within scan block }
__device__ uint2        g_bp[WORDS];
__device__ unsigned int g_blockSums[SCAN_BLOCKS];
__device__ unsigned int g_blockOffsets[SCAN_BLOCKS];
__device__ unsigned int g_keyflag[MAXN];        // key | (isFirst << 31) per point
__device__ unsigned int g_dupList[MAXN];        // point indices of non-first duplicates
__device__ unsigned int g_dupCount;
__device__ unsigned int g_totalUnique;
__device__ unsigned int g_scanDone;

// ---------------------------------------------------------------------------
// 0) zero bit/prefix pairs + counters (graph replays reuse the globals)
__global__ void zero_bitmap_kernel() {
    unsigned i = blockIdx.x * blockDim.x + threadIdx.x;   // WORDS*8/16 uint4 stores
    ((uint4*)g_bp)[i] = make_uint4(0, 0, 0, 0);
    if (i == 0) { g_dupCount = 0; g_scanDone = 0; }
}

__device__ __forceinline__ unsigned make_key(int4 c) {
    return (unsigned)(((c.x * 64 + c.y) * 64 + c.z) * 64 + c.w);   // < 2^24
}

// 1) mark key presence; classify each point as first-setter or duplicate
__global__ void set_bits_kernel(const int4* __restrict__ coords, int n) {
    int i = blockIdx.x * blockDim.x + threadIdx.x;
    if (i >= n) return;
    unsigned key = make_key(coords[i]);
    unsigned bit = 1u << (key & 31);
    unsigned old = atomicOr(&g_bp[key >> 5].x, bit);
    bool first = (old & bit) == 0u;
    g_keyflag[i] = key | (first ? 0x80000000u : 0u);
    if (!first) {
        unsigned d = atomicAdd(&g_dupCount, 1u);
        g_dupList[d] = (unsigned)i;
    }
}

// 2) fused hierarchical scan. Only block 0 spins after publishing -> safe.
__global__ void fused_scan_kernel() {
    __shared__ unsigned warpSums[32];
    unsigned w = blockIdx.x * SCAN_THREADS + threadIdx.x;
    unsigned p = __popc(g_bp[w].x);

    unsigned v = p;
    int lane = threadIdx.x & 31;
    int warp = threadIdx.x >> 5;
    #pragma unroll
    for (int d = 1; d < 32; d <<= 1) {
        unsigned t = __shfl_up_sync(0xffffffffu, v, d);
        if (lane >= d) v += t;
    }
    if (lane == 31) warpSums[warp] = v;
    __syncthreads();
    if (warp == 0) {
        unsigned s = warpSums[lane];
        #pragma unroll
        for (int d = 1; d < 32; d <<= 1) {
            unsigned t = __shfl_up_sync(0xffffffffu, s, d);
            if (lane >= d) s += t;
        }
        warpSums[lane] = s;
    }
    __syncthreads();
    unsigned base = (warp > 0) ? warpSums[warp - 1] : 0u;
    g_bp[w].y = base + v - p;                              // local exclusive prefix
    if (threadIdx.x == SCAN_THREADS - 1) {
        g_blockSums[blockIdx.x] = base + v;
        __threadfence();
        atomicAdd(&g_scanDone, 1u);
    }

    if (blockIdx.x == 0 && warp == 0) {
        if (lane == 0) {
            while (atomicAdd(&g_scanDone, 0u) < SCAN_BLOCKS) { /* spin */ }
        }
        __syncwarp();
        __threadfence();
        unsigned loc[16];
        unsigned mySum = 0;
        #pragma unroll
        for (int j = 0; j < 16; j++) {
            loc[j] = g_blockSums[lane * 16 + j];
            mySum += loc[j];
        }
        unsigned inc = mySum;
        #pragma unroll
        for (int d = 1; d < 32; d <<= 1) {
            unsigned t = __shfl_up_sync(0xffffffffu, inc, d);
            if (lane >= d) inc += t;
        }
        unsigned run = inc - mySum;
        #pragma unroll
        for (int j = 0; j < 16; j++) {
            g_blockOffsets[lane * 16 + j] = run;
            run += loc[j];
        }
        if (lane == 31) g_totalUnique = run;
    }
}

// ---------------------------------------------------------------------------
// 3) first-setter scatter: 8 lanes per row, 8 rows per warp (2 unrolled iters).
//    rank chain: keyflag (coalesced) -> one LDG.64 g_bp (L2 hit) -> smem offs.
__global__ __launch_bounds__(256) void scatter_first_kernel(
        const float4* __restrict__ feat4, float4* __restrict__ out4, int n) {
    __shared__ unsigned offs[SCAN_BLOCKS];
    offs[threadIdx.x]       = g_blockOffsets[threadIdx.x];
    offs[threadIdx.x + 256] = g_blockOffsets[threadIdx.x + 256];
    __syncthreads();

    int gtid = blockIdx.x * blockDim.x + threadIdx.x;
    int wid  = gtid >> 5;
    int lane = gtid & 31;
    int sub  = lane >> 3;             // 4 row-groups per warp per iter
    int j    = lane & 7;              // float4 index within 128B row
    int src  = lane & ~7;             // leader lane of this 8-lane group
    unsigned U = g_totalUnique;

    int row0 = wid * 8 + sub;         // iter 0
    int row1 = row0 + 4;              // iter 1
    bool ok0 = row0 < n, ok1 = row1 < n;

    // leaders fetch keyflags for both rows (coalesced)
    unsigned kf0 = 0, kf1 = 0;
    if (j == 0) {
        if (ok0) kf0 = g_keyflag[row0];
        if (ok1) kf1 = g_keyflag[row1];
    }
    // leaders fetch bit/prefix pairs (single 8B L2 load each)
    unsigned rank0 = 0, rank1 = 0;
    if (j == 0) {
        if (kf0 & 0x80000000u) {
            unsigned key = kf0 & 0x00FFFFFFu, w = key >> 5;
            uint2 bp = g_bp[w];
            rank0 = offs[w >> 10] + bp.y + __popc(bp.x & ((1u << (key & 31)) - 1u));
        }
        if (kf1 & 0x80000000u) {
            unsigned key = kf1 & 0x00FFFFFFu, w = key >> 5;
            uint2 bp = g_bp[w];
            rank1 = offs[w >> 10] + bp.y + __popc(bp.x & ((1u << (key & 31)) - 1u));
        }
    }
    kf0   = __shfl_sync(0xffffffffu, kf0, src);
    kf1   = __shfl_sync(0xffffffffu, kf1, src);
    rank0 = __shfl_sync(0xffffffffu, rank0, src);
    rank1 = __shfl_sync(0xffffffffu, rank1, src);

    // feature loads (independent of rank chain; coalesced)
    float4 f0, f1;
    if (ok0 && (kf0 & 0x80000000u)) f0 = feat4[(size_t)row0 * 8 + j];
    if (ok1 && (kf1 & 0x80000000u)) f1 = feat4[(size_t)row1 * 8 + j];

    // padding rows (disjoint from scatter targets: rank < U <= row)
    float4 z = make_float4(0.f, 0.f, 0.f, 0.f);
    if (ok0 && (unsigned)row0 >= U) out4[(size_t)row0 * 8 + j] = z;
    if (ok1 && (unsigned)row1 >= U) out4[(size_t)row1 * 8 + j] = z;

    if (ok0 && (kf0 & 0x80000000u)) out4[(size_t)rank0 * 8 + j] = f0;
    if (ok1 && (kf1 & 0x80000000u)) out4[(size_t)rank1 * 8 + j] = f1;
}

// 4) duplicates (~3%): atomicAdd after base stores (launch-ordered)
__global__ void scatter_dups_kernel(const float* __restrict__ feat,
                                    float* __restrict__ out) {
    unsigned totalWarps = (gridDim.x * blockDim.x) >> 5;
    unsigned wid  = (blockIdx.x * blockDim.x + threadIdx.x) >> 5;
    int lane = threadIdx.x & 31;
    unsigned cnt = g_dupCount;
    for (unsigned j = wid; j < cnt; j += totalWarps) {
        unsigned p = 0, rank = 0;
        if (lane == 0) {
            p = g_dupList[j];
            unsigned key = g_keyflag[p] & 0x00FFFFFFu, w = key >> 5;
            uint2 bp = g_bp[w];
            rank = g_blockOffsets[w >> 10] + bp.y +
                   __popc(bp.x & ((1u << (key & 31)) - 1u));
        }
        p    = __shfl_sync(0xffffffffu, p, 0);
        rank = __shfl_sync(0xffffffffu, rank, 0);
        atomicAdd(&out[(size_t)rank * 32 + lane], feat[(size_t)p * 32 + lane]);
    }
}

// ---------------------------------------------------------------------------
extern "C" void kernel_launch(void* const* d_in, const int* in_sizes, int n_in,
                              void* d_out, int out_size) {
    const int4*  coords = (const int4*)d_in[0];    // [N,4] int32
    const float* feat   = (const float*)d_in[1];   // [N,32] float32
    float*       out    = (float*)d_out;           // [N,32] float32
    int n = in_sizes[0] / 4;

    zero_bitmap_kernel<<<(WORDS * 8 / 16) / 256, 256>>>();
    set_bits_kernel<<<(n + 255) / 256, 256>>>(coords, n);
    fused_scan_kernel<<<SCAN_BLOCKS, SCAN_THREADS>>>();
    int blocks = (n + 63) / 64;       // 8 warps/block * 8 rows/warp
    scatter_first_kernel<<<blocks, 256>>>((const float4*)feat, (float4*)out, n);
    scatter_dups_kernel<<<512, 256>>>(feat, out);
}